// round 4
// baseline (speedup 1.0000x reference)
#include <cuda_runtime.h>

#define Nn 20000
#define Ee 160000

typedef unsigned long long ull;

// ---------------- scratch (device globals: allocation-free) ----------------
__device__ float g_h[Nn * 256];      // per node: [u][ h0, h1x, h1y, h1z ] interleaved
__device__ float g_sc[Nn * 320];     // [sc0(128) | sc1 as w*3+d (192)]
__device__ int   g_cnt[Nn];
__device__ int   g_cur[Nn];
__device__ int   g_off[Nn + 1];
__device__ int   g_eperm[Ee];

__device__ __forceinline__ float silu_f(float x) { return x / (1.0f + __expf(-x)); }

// ---- packed f32x2 helpers (sm_100+) ----
__device__ __forceinline__ ull pk2(float x, float y) {
    ull r; asm("mov.b64 %0, {%1,%2};" : "=l"(r) : "f"(x), "f"(y)); return r;
}
__device__ __forceinline__ ull dup2(float x) {
    ull r; asm("mov.b64 %0, {%1,%1};" : "=l"(r) : "f"(x)); return r;
}
__device__ __forceinline__ void fma2(ull& acc, ull a, ull b) {
    asm("fma.rn.f32x2 %0, %1, %2, %0;" : "+l"(acc) : "l"(a), "l"(b));
}
__device__ __forceinline__ ull mul2(ull a, ull b) {
    ull r; asm("mul.rn.f32x2 %0, %1, %2;" : "=l"(r) : "l"(a), "l"(b)); return r;
}
__device__ __forceinline__ float2 up2(ull v) {
    float2 f; asm("mov.b64 {%0,%1}, %2;" : "=f"(f.x), "=f"(f.y) : "l"(v)); return f;
}

extern __shared__ float smem_dyn[];

// ---------------- CSR build ----------------
__global__ void k_zero() {
    int i = blockIdx.x * blockDim.x + threadIdx.x;
    if (i < Nn) { g_cnt[i] = 0; g_cur[i] = 0; }
}

__global__ void k_hist(const int* __restrict__ ei) {
    for (int e = blockIdx.x * blockDim.x + threadIdx.x; e < Ee; e += gridDim.x * blockDim.x)
        atomicAdd(&g_cnt[ei[Ee + e]], 1);
}

__global__ void k_scan() {
    __shared__ int sh[1024];
    __shared__ int carry;
    int t = threadIdx.x;
    if (t == 0) carry = 0;
    __syncthreads();
    for (int base = 0; base < Nn; base += 1024) {
        int v = (base + t < Nn) ? g_cnt[base + t] : 0;
        sh[t] = v;
        __syncthreads();
        for (int off = 1; off < 1024; off <<= 1) {
            int x = (t >= off) ? sh[t - off] : 0;
            __syncthreads();
            sh[t] += x;
            __syncthreads();
        }
        if (base + t < Nn) g_off[base + t] = carry + sh[t] - v;  // exclusive
        __syncthreads();
        if (t == 0) carry += sh[1023];
        __syncthreads();
    }
    if (t == 0) g_off[Nn] = carry;
}

__global__ void k_scatter(const int* __restrict__ ei) {
    for (int e = blockIdx.x * blockDim.x + threadIdx.x; e < Ee; e += gridDim.x * blockDim.x) {
        int dst = ei[Ee + e];
        int pos = g_off[dst] + atomicAdd(&g_cur[dst], 1);
        g_eperm[pos] = e;
    }
}

// ---------------- h = lin1(node_feats), interleaved output layout ----------------
__global__ void k_h(const float* __restrict__ nf,
                    const float* __restrict__ W10, const float* __restrict__ W11) {
    __shared__ float w10[4096], w11[4096], xs[256], os[256];
    int t = threadIdx.x;
    for (int i = t; i < 4096; i += 256) { w10[i] = W10[i]; w11[i] = W11[i]; }
    __syncthreads();
    for (int n = blockIdx.x; n < Nn; n += gridDim.x) {
        xs[t] = nf[(size_t)n * 256 + t];
        __syncthreads();
        float acc = 0.f;
        if (t < 64) {
            #pragma unroll 8
            for (int k = 0; k < 64; k++) acc += xs[k] * w10[k * 64 + t];
            os[t * 4] = acc * 0.125f;                     // h0[u] -> slot u*4
        } else {
            int i = t - 64, d = i >> 6, v = i & 63;
            #pragma unroll 8
            for (int k = 0; k < 64; k++) acc += xs[64 + k * 3 + d] * w11[k * 64 + v];
            os[v * 4 + 1 + d] = acc * 0.125f;             // h1[v][d] -> slot v*4+1+d
        }
        __syncthreads();
        g_h[(size_t)n * 256 + t] = os[t];
        __syncthreads();
    }
}

// ---------------- sc (skip connection): warp x 4 nodes, f32x2 math ----------------
__global__ void k_sc(const float* __restrict__ nf, const float* __restrict__ na,
                     const float* __restrict__ Wsc0, const float* __restrict__ Wsc1) {
    float* wsc0T = smem_dyn;           // 32768 floats, layout [u][w128][z4]
    float* wsc1  = wsc0T + 32768;      // 16384 floats, layout [u][z][w64]
    float* xsb   = wsc1 + 16384;       // 8 warps * 4 nodes * 256 floats
    int t = threadIdx.x;               // 256 threads
    for (int i = t; i < 32768; i += 256) {
        int u = i >> 9, z = (i >> 7) & 3, w = i & 127;
        wsc0T[(u * 128 + w) * 4 + z] = Wsc0[i];
    }
    for (int i = t; i < 16384; i += 256) wsc1[i] = Wsc1[i];
    __syncthreads();
    int wid = t >> 5, lane = t & 31;
    float* xs = xsb + wid * 1024;
    int warps = gridDim.x * 8;
    const float inv_sc = 0.0625f;      // 1/sqrt(64*4)
    const ulonglong2* wT = (const ulonglong2*)wsc0T;   // index u*128 + w
    const ull* w1u = (const ull*)wsc1;                 // index (u*4+z)*32 + lane

    for (int nb = (blockIdx.x * 8 + wid) * 4; nb < Nn; nb += warps * 4) {
        __syncwarp();
        // stage 4 x-rows
        #pragma unroll
        for (int nn = 0; nn < 4; nn++) {
            int n = nb + nn;
            if (n < Nn) {
                const float4* src = (const float4*)(nf + (size_t)n * 256);
                float4* dst = (float4*)(xs + nn * 256);
                dst[lane] = src[lane];
                dst[lane + 32] = src[lane + 32];
            }
        }
        float naz[4][4];
        ull nazp[4][2];    // z-pairs (z0,z1),(z2,z3)
        ull nazd[4][4];    // duplicated
        #pragma unroll
        for (int nn = 0; nn < 4; nn++) {
            int n = (nb + nn < Nn) ? nb + nn : 0;
            float4 v = *(const float4*)(na + (size_t)n * 4);
            naz[nn][0] = v.x; naz[nn][1] = v.y; naz[nn][2] = v.z; naz[nn][3] = v.w;
            nazp[nn][0] = pk2(v.x, v.y); nazp[nn][1] = pk2(v.z, v.w);
            nazd[nn][0] = dup2(v.x); nazd[nn][1] = dup2(v.y);
            nazd[nn][2] = dup2(v.z); nazd[nn][3] = dup2(v.w);
        }
        __syncwarp();

        // ---- sc0: acc0[nn][k] f32x2 over z-parity; lane owns w = lane + 32k ----
        ull acc0[4][4];
        #pragma unroll
        for (int nn = 0; nn < 4; nn++)
            #pragma unroll
            for (int k = 0; k < 4; k++) acc0[nn][k] = 0ull;
        for (int u = 0; u < 64; u++) {
            ull y01[4], y23[4];
            #pragma unroll
            for (int nn = 0; nn < 4; nn++) {
                ull xd = dup2(xs[nn * 256 + u]);
                y01[nn] = mul2(xd, nazp[nn][0]);
                y23[nn] = mul2(xd, nazp[nn][1]);
            }
            #pragma unroll
            for (int k = 0; k < 4; k++) {
                ulonglong2 wz = wT[u * 128 + lane + 32 * k];
                #pragma unroll
                for (int nn = 0; nn < 4; nn++) {
                    fma2(acc0[nn][k], y01[nn], wz.x);
                    fma2(acc0[nn][k], y23[nn], wz.y);
                }
            }
        }

        // ---- sc1: wr = sum_z na[z]*W1 (f32x2 over w-pair), a1 += wr * x1[u][d] ----
        ull a1[4][3];
        #pragma unroll
        for (int nn = 0; nn < 4; nn++)
            #pragma unroll
            for (int d = 0; d < 3; d++) a1[nn][d] = 0ull;
        for (int u = 0; u < 64; u++) {
            ull wz0 = w1u[(u * 4 + 0) * 32 + lane];
            ull wz1 = w1u[(u * 4 + 1) * 32 + lane];
            ull wz2 = w1u[(u * 4 + 2) * 32 + lane];
            ull wz3 = w1u[(u * 4 + 3) * 32 + lane];
            #pragma unroll
            for (int nn = 0; nn < 4; nn++) {
                ull wr = mul2(nazd[nn][0], wz0);
                fma2(wr, nazd[nn][1], wz1);
                fma2(wr, nazd[nn][2], wz2);
                fma2(wr, nazd[nn][3], wz3);
                #pragma unroll
                for (int d = 0; d < 3; d++)
                    fma2(a1[nn][d], wr, dup2(xs[nn * 256 + 64 + u * 3 + d]));
            }
        }

        // stores
        #pragma unroll
        for (int nn = 0; nn < 4; nn++) {
            int n = nb + nn;
            if (n >= Nn) continue;
            float* s0o = g_sc + (size_t)n * 320;
            #pragma unroll
            for (int k = 0; k < 4; k++) {
                float2 f = up2(acc0[nn][k]);
                s0o[lane + 32 * k] = (f.x + f.y) * inv_sc;
            }
            float* o = g_sc + (size_t)n * 320 + 128 + lane * 6;
            float2 d0 = up2(a1[nn][0]), d1 = up2(a1[nn][1]), d2 = up2(a1[nn][2]);
            o[0] = d0.x * inv_sc; o[1] = d1.x * inv_sc; o[2] = d2.x * inv_sc;
            o[3] = d0.y * inv_sc; o[4] = d1.y * inv_sc; o[5] = d2.y * inv_sc;
        }
    }
}

// ---------------- fused gather-reduce + lin2 + skip + gate + output ----------------
__global__ void k_final(const float* __restrict__ nf, const float* __restrict__ ea,
                        const float* __restrict__ emb, const float* __restrict__ Wm1,
                        const float* __restrict__ Wm2, const float* __restrict__ Wl20,
                        const float* __restrict__ Wl21, const int* __restrict__ ei,
                        float* __restrict__ out) {
    float* wl20 = smem_dyn;          // 16384 floats
    float* wl21 = wl20 + 16384;      // 8192
    float* wm2  = wl21 + 8192;       // 2048, layout [j][u][4] = (w1,w2,w3,w4)
    float* wm1  = wm2 + 2048;        // 64
    float* stg  = wm1 + 64;          // 8 warps * 4 nodes * 512
    int t = threadIdx.x;             // 256
    for (int i = t; i < 16384; i += 256) wl20[i] = Wl20[i];
    for (int i = t; i < 8192; i += 256) wl21[i] = Wl21[i];
    for (int i = t; i < 2048; i += 256) {
        int j = i >> 8, r = i & 255, c = r >> 6, u = r & 63;
        wm2[(j * 64 + u) * 4 + c] = Wm2[i];
    }
    if (t < 64) wm1[t] = Wm1[t];
    __syncthreads();

    int wid = t >> 5, lane = t & 31;
    float* stw = stg + wid * 2048;   // 4 nodes * 512
    const float inv_e = 0.35355339059327373f;   // 1/sqrt(8)
    const float inv_n = 0.35355339059327373f;   // 1/sqrt(8)
    const float inv2  = 0.08838834764831845f;   // 1/sqrt(128)
    const float is3   = 0.5773502691896258f;    // 1/sqrt(3)
    int warps = gridDim.x * 8;
    const ulonglong2* wm2v = (const ulonglong2*)wm2;   // index j*64+u -> (w1,w2),(w3,w4)

    for (int nb = (blockIdx.x * 8 + wid) * 4; nb < Nn; nb += warps * 4) {
        __syncwarp();
        // ---- edge reduction phase: 4 nodes sequentially ----
        #pragma unroll 1
        for (int nn = 0; nn < 4; nn++) {
            int n = nb + nn;
            int beg = (n < Nn) ? g_off[n] : 0;
            int end = (n < Nn) ? g_off[n + 1] : 0;
            float s0a[2] = {0, 0}, s0b[2] = {0, 0};
            float s1a[2][3] = {{0, 0, 0}, {0, 0, 0}};
            float s1b[2][3] = {{0, 0, 0}, {0, 0, 0}};

            int e_next = 0, src_next = 0;
            if (beg < end) { e_next = g_eperm[beg]; src_next = ei[e_next]; }
            for (int i = beg; i < end; i++) {
                int e = e_next, src = src_next;
                if (i + 1 < end) { e_next = g_eperm[i + 1]; src_next = ei[e_next]; }
                // hid = silu(emb @ Wm1 * inv_e): lanes 0..7 compute, broadcast
                float hv = 0.f;
                if (lane < 8) {
                    const float4* ep = (const float4*)(emb + (size_t)e * 8);
                    float4 e0 = ep[0], e1 = ep[1];
                    float a = e0.x * wm1[0 * 8 + lane] + e0.y * wm1[1 * 8 + lane]
                            + e0.z * wm1[2 * 8 + lane] + e0.w * wm1[3 * 8 + lane]
                            + e1.x * wm1[4 * 8 + lane] + e1.y * wm1[5 * 8 + lane]
                            + e1.z * wm1[6 * 8 + lane] + e1.w * wm1[7 * 8 + lane];
                    hv = silu_f(a * inv_e);
                }
                ull hdup[8];
                #pragma unroll
                for (int j = 0; j < 8; j++) hdup[j] = dup2(__shfl_sync(0xffffffffu, hv, j));
                float4 eav = *(const float4*)(ea + (size_t)e * 4);
                const float4* hp = (const float4*)(g_h + (size_t)src * 256);
                #pragma unroll
                for (int p = 0; p < 2; p++) {
                    int u = lane + p * 32;
                    float4 hvv = hp[u];  // (h0, h1x, h1y, h1z)
                    ull a12 = 0ull, a34 = 0ull;
                    #pragma unroll
                    for (int j = 0; j < 8; j++) {
                        ulonglong2 wv = wm2v[j * 64 + u];
                        fma2(a12, hdup[j], wv.x);
                        fma2(a34, hdup[j], wv.y);
                    }
                    float2 w12 = up2(a12), w34 = up2(a34);
                    float w1 = w12.x * inv_e, w2 = w12.y * inv_e;
                    float w3 = w34.x * inv_e, w4 = w34.y * inv_e;
                    float g0 = hvv.x, gx = hvv.y, gy = hvv.z, gz = hvv.w;
                    s0a[p] += w1 * g0 * eav.x;
                    s0b[p] += w4 * (gx * eav.y + gy * eav.z + gz * eav.w) * is3;
                    float c = w2 * g0;
                    s1a[p][0] += c * eav.y; s1a[p][1] += c * eav.z; s1a[p][2] += c * eav.w;
                    float b = w3 * eav.x;
                    s1b[p][0] += b * gx; s1b[p][1] += b * gy; s1b[p][2] += b * gz;
                }
            }
            // stage s into shared (s0[128] | s1 as k*3+d [384])
            float* st = stw + nn * 512;
            #pragma unroll
            for (int p = 0; p < 2; p++) {
                int u = lane + p * 32;
                st[u]      = s0a[p] * inv_n;
                st[64 + u] = s0b[p] * inv_n;
                #pragma unroll
                for (int d = 0; d < 3; d++) {
                    st[128 + u * 3 + d]        = s1a[p][d] * inv_n;
                    st[128 + (64 + u) * 3 + d] = s1b[p][d] * inv_n;
                }
            }
        }
        __syncwarp();

        // ---- lin2 phase: shared weight stream, f32x2 ----
        ull t0lo[4], t0hi[4];
        #pragma unroll
        for (int nn = 0; nn < 4; nn++) { t0lo[nn] = 0ull; t0hi[nn] = 0ull; }
        const ulonglong2* wp = (const ulonglong2*)wl20;
        for (int k = 0; k < 128; k++) {
            ulonglong2 wv = wp[k * 32 + lane];
            #pragma unroll
            for (int nn = 0; nn < 4; nn++) {
                ull sd = dup2(stw[nn * 512 + k]);
                fma2(t0lo[nn], sd, wv.x);
                fma2(t0hi[nn], sd, wv.y);
            }
        }
        ull t1v[4][3];
        #pragma unroll
        for (int nn = 0; nn < 4; nn++)
            #pragma unroll
            for (int d = 0; d < 3; d++) t1v[nn][d] = 0ull;
        const ull* wq = (const ull*)wl21;
        for (int k = 0; k < 128; k++) {
            ull wv = wq[k * 32 + lane];
            #pragma unroll
            for (int nn = 0; nn < 4; nn++) {
                const float* sb = stw + nn * 512 + 128 + k * 3;
                fma2(t1v[nn][0], wv, dup2(sb[0]));
                fma2(t1v[nn][1], wv, dup2(sb[1]));
                fma2(t1v[nn][2], wv, dup2(sb[2]));
            }
        }
        __syncwarp();

        // ---- output phase per node ----
        #pragma unroll 1
        for (int nn = 0; nn < 4; nn++) {
            int n = nb + nn;
            if (n >= Nn) continue;
            float* st = stw + nn * 512;
            float2 tl = up2(t0lo[nn]), th = up2(t0hi[nn]);
            float4 sc0 = ((const float4*)(g_sc + (size_t)n * 320))[lane];
            float4 tt;
            tt.x = tl.x * inv2 + sc0.x; tt.y = tl.y * inv2 + sc0.y;
            tt.z = th.x * inv2 + sc0.z; tt.w = th.y * inv2 + sc0.w;
            int wbase = lane * 4;
            if (wbase < 64) {
                float4 nfv = ((const float4*)(nf + (size_t)n * 256))[lane];
                float4 ov;
                ov.x = nfv.x + silu_f(tt.x); ov.y = nfv.y + silu_f(tt.y);
                ov.z = nfv.z + silu_f(tt.z); ov.w = nfv.w + silu_f(tt.w);
                ((float4*)(out + (size_t)n * 256))[lane] = ov;
            } else {
                int u = wbase - 64;
                st[u]     = silu_f(tt.x);
                st[u + 1] = silu_f(tt.y);
                st[u + 2] = silu_f(tt.z);
                st[u + 3] = silu_f(tt.w);
            }
            __syncwarp();
            int w = lane * 2;
            const float* sc1 = g_sc + (size_t)n * 320 + 128;
            float2 t1d[3] = { up2(t1v[nn][0]), up2(t1v[nn][1]), up2(t1v[nn][2]) };
            float gate0 = st[w], gate1 = st[w + 1];
            float* ob = out + (size_t)n * 256;
            const float* nb2 = nf + (size_t)n * 256;
            #pragma unroll
            for (int d = 0; d < 3; d++) {
                int c0 = 64 + w * 3 + d, c1 = 64 + (w + 1) * 3 + d;
                ob[c0] = nb2[c0] + gate0 * (t1d[d].x * inv2 + sc1[w * 3 + d]);
                ob[c1] = nb2[c1] + gate1 * (t1d[d].y * inv2 + sc1[(w + 1) * 3 + d]);
            }
            __syncwarp();
        }
    }
}

// ---------------- host ----------------
extern "C" void kernel_launch(void* const* d_in, const int* in_sizes, int n_in,
                              void* d_out, int out_size) {
    const float* nf   = (const float*)d_in[0];
    const float* na   = (const float*)d_in[1];
    const float* ea   = (const float*)d_in[2];
    const float* emb  = (const float*)d_in[3];
    const float* W10  = (const float*)d_in[4];
    const float* W11  = (const float*)d_in[5];
    const float* Wm1  = (const float*)d_in[6];
    const float* Wm2  = (const float*)d_in[7];
    const float* Wl20 = (const float*)d_in[8];
    const float* Wl21 = (const float*)d_in[9];
    const float* Wsc0 = (const float*)d_in[10];
    const float* Wsc1 = (const float*)d_in[11];
    const int*   ei   = (const int*)d_in[12];
    float* out = (float*)d_out;

    cudaFuncSetAttribute(k_sc,    cudaFuncAttributeMaxDynamicSharedMemorySize, 229376);
    cudaFuncSetAttribute(k_final, cudaFuncAttributeMaxDynamicSharedMemorySize, 172288);

    k_zero<<<(Nn + 255) / 256, 256>>>();
    k_hist<<<512, 256>>>(ei);
    k_scan<<<1, 1024>>>();
    k_scatter<<<512, 256>>>(ei);
    k_h<<<1024, 256>>>(nf, W10, W11);
    k_sc<<<148, 256, 229376>>>(nf, na, Wsc0, Wsc1);
    k_final<<<148, 256, 172288>>>(nf, ea, emb, Wm1, Wm2, Wl20, Wl21, ei, out);
}

// round 5
// speedup vs baseline: 2.1633x; 2.1633x over previous
#include <cuda_runtime.h>

#define Nn 20000
#define Ee 160000

// ---------------- scratch (device globals: allocation-free) ----------------
__device__ float g_h[Nn * 256];      // per node: [u][ h0, h1x, h1y, h1z ] interleaved
__device__ float g_sc[Nn * 320];     // [sc0(128) | sc1 as w*3+d (192)]
__device__ int   g_cnt[Nn];
__device__ int   g_cur[Nn];
__device__ int   g_off[Nn + 1];
__device__ int   g_eperm[Ee];

__device__ __forceinline__ float silu_f(float x) { return x / (1.0f + __expf(-x)); }

extern __shared__ float smem_dyn[];

// ---------------- CSR build ----------------
__global__ void k_zero() {
    int i = blockIdx.x * blockDim.x + threadIdx.x;
    if (i < Nn) { g_cnt[i] = 0; g_cur[i] = 0; }
}

__global__ void k_hist(const int* __restrict__ ei) {
    for (int e = blockIdx.x * blockDim.x + threadIdx.x; e < Ee; e += gridDim.x * blockDim.x)
        atomicAdd(&g_cnt[ei[Ee + e]], 1);
}

__global__ void k_scan() {
    __shared__ int sh[1024];
    __shared__ int carry;
    int t = threadIdx.x;
    if (t == 0) carry = 0;
    __syncthreads();
    for (int base = 0; base < Nn; base += 1024) {
        int v = (base + t < Nn) ? g_cnt[base + t] : 0;
        sh[t] = v;
        __syncthreads();
        for (int off = 1; off < 1024; off <<= 1) {
            int x = (t >= off) ? sh[t - off] : 0;
            __syncthreads();
            sh[t] += x;
            __syncthreads();
        }
        if (base + t < Nn) g_off[base + t] = carry + sh[t] - v;  // exclusive
        __syncthreads();
        if (t == 0) carry += sh[1023];
        __syncthreads();
    }
    if (t == 0) g_off[Nn] = carry;
}

__global__ void k_scatter(const int* __restrict__ ei) {
    for (int e = blockIdx.x * blockDim.x + threadIdx.x; e < Ee; e += gridDim.x * blockDim.x) {
        int dst = ei[Ee + e];
        int pos = g_off[dst] + atomicAdd(&g_cur[dst], 1);
        g_eperm[pos] = e;
    }
}

// ---------------- h = lin1(node_feats), interleaved output layout ----------------
__global__ void k_h(const float* __restrict__ nf,
                    const float* __restrict__ W10, const float* __restrict__ W11) {
    __shared__ float w10[4096], w11[4096], xs[256], os[256];
    int t = threadIdx.x;
    for (int i = t; i < 4096; i += 256) { w10[i] = W10[i]; w11[i] = W11[i]; }
    __syncthreads();
    for (int n = blockIdx.x; n < Nn; n += gridDim.x) {
        xs[t] = nf[(size_t)n * 256 + t];
        __syncthreads();
        float acc = 0.f;
        if (t < 64) {
            #pragma unroll 8
            for (int k = 0; k < 64; k++) acc += xs[k] * w10[k * 64 + t];
            os[t * 4] = acc * 0.125f;                     // h0[u] -> slot u*4
        } else {
            int i = t - 64, d = i >> 6, v = i & 63;
            #pragma unroll 8
            for (int k = 0; k < 64; k++) acc += xs[64 + k * 3 + d] * w11[k * 64 + v];
            os[v * 4 + 1 + d] = acc * 0.125f;             // h1[v][d] -> slot v*4+1+d
        }
        __syncthreads();
        g_h[(size_t)n * 256 + t] = os[t];
        __syncthreads();
    }
}

// ---------------- sc (skip connection): 512 thr, 16 warps/SM, warp x 2 nodes ----------
__global__ __launch_bounds__(512, 1)
void k_sc(const float* __restrict__ nf, const float* __restrict__ na,
          const float* __restrict__ Wsc0, const float* __restrict__ Wsc1) {
    float* wsc0 = smem_dyn;            // 32768 floats (128KB), [u][z][w128]
    float* wsc1 = wsc0 + 32768;        // 16384 floats (64KB),  [u][z][w64]
    float* xsb  = wsc1 + 16384;        // 16 warps * 2 nodes * 256 floats (32KB)
    int t = threadIdx.x;               // 512 threads
    for (int i = t; i < 32768; i += 512) wsc0[i] = Wsc0[i];
    for (int i = t; i < 16384; i += 512) wsc1[i] = Wsc1[i];
    __syncthreads();
    int wid = t >> 5, lane = t & 31;
    float* xs = xsb + wid * 512;
    int warps = gridDim.x * 16;
    const float inv_sc = 0.0625f;      // 1/sqrt(64*4)
    const float4* w0 = (const float4*)wsc0;
    const float2* w1 = (const float2*)wsc1;

    for (int nb = (blockIdx.x * 16 + wid) * 2; nb < Nn; nb += warps * 2) {
        __syncwarp();
        // stage 2 x-rows
        #pragma unroll
        for (int nn = 0; nn < 2; nn++) {
            int n = nb + nn;
            if (n < Nn) {
                const float4* src = (const float4*)(nf + (size_t)n * 256);
                float4* dst = (float4*)(xs + nn * 256);
                dst[lane] = src[lane];
                dst[lane + 32] = src[lane + 32];
            }
        }
        float naz[2][4];
        #pragma unroll
        for (int nn = 0; nn < 2; nn++) {
            int n = (nb + nn < Nn) ? nb + nn : 0;
            float4 v = *(const float4*)(na + (size_t)n * 4);
            naz[nn][0] = v.x; naz[nn][1] = v.y; naz[nn][2] = v.z; naz[nn][3] = v.w;
        }
        __syncwarp();

        // ---- sc0: acc0[nn][w4] = sum_{u,z} x0[u]*na[z]*W0[u,z,w] ----
        float4 acc0[2];
        #pragma unroll
        for (int nn = 0; nn < 2; nn++) acc0[nn] = make_float4(0, 0, 0, 0);
        #pragma unroll 4
        for (int u = 0; u < 64; u++) {
            float xv0 = xs[u], xv1 = xs[256 + u];
            #pragma unroll
            for (int z = 0; z < 4; z++) {
                float4 wv = w0[(u * 4 + z) * 32 + lane];
                float y0 = xv0 * naz[0][z];
                float y1 = xv1 * naz[1][z];
                acc0[0].x += y0 * wv.x; acc0[0].y += y0 * wv.y;
                acc0[0].z += y0 * wv.z; acc0[0].w += y0 * wv.w;
                acc0[1].x += y1 * wv.x; acc0[1].y += y1 * wv.y;
                acc0[1].z += y1 * wv.z; acc0[1].w += y1 * wv.w;
            }
        }

        // ---- sc1: wr = sum_z na[z]*W1[u,z,w2]; acc1 += wr ⊗ x1[u][d] ----
        float a1[2][2][3];
        #pragma unroll
        for (int nn = 0; nn < 2; nn++)
            #pragma unroll
            for (int p = 0; p < 2; p++)
                #pragma unroll
                for (int d = 0; d < 3; d++) a1[nn][p][d] = 0.f;
        #pragma unroll 4
        for (int u = 0; u < 64; u++) {
            float2 wz0 = w1[(u * 4 + 0) * 32 + lane];
            float2 wz1 = w1[(u * 4 + 1) * 32 + lane];
            float2 wz2 = w1[(u * 4 + 2) * 32 + lane];
            float2 wz3 = w1[(u * 4 + 3) * 32 + lane];
            #pragma unroll
            for (int nn = 0; nn < 2; nn++) {
                float wrx = naz[nn][0] * wz0.x + naz[nn][1] * wz1.x
                          + naz[nn][2] * wz2.x + naz[nn][3] * wz3.x;
                float wry = naz[nn][0] * wz0.y + naz[nn][1] * wz1.y
                          + naz[nn][2] * wz2.y + naz[nn][3] * wz3.y;
                float gx = xs[nn * 256 + 64 + u * 3];
                float gy = xs[nn * 256 + 64 + u * 3 + 1];
                float gz = xs[nn * 256 + 64 + u * 3 + 2];
                a1[nn][0][0] += wrx * gx; a1[nn][0][1] += wrx * gy; a1[nn][0][2] += wrx * gz;
                a1[nn][1][0] += wry * gx; a1[nn][1][1] += wry * gy; a1[nn][1][2] += wry * gz;
            }
        }

        // stores
        #pragma unroll
        for (int nn = 0; nn < 2; nn++) {
            int n = nb + nn;
            if (n >= Nn) continue;
            float4 r0;
            r0.x = acc0[nn].x * inv_sc; r0.y = acc0[nn].y * inv_sc;
            r0.z = acc0[nn].z * inv_sc; r0.w = acc0[nn].w * inv_sc;
            ((float4*)(g_sc + (size_t)n * 320))[lane] = r0;
            float* o = g_sc + (size_t)n * 320 + 128 + lane * 6;
            o[0] = a1[nn][0][0] * inv_sc; o[1] = a1[nn][0][1] * inv_sc;
            o[2] = a1[nn][0][2] * inv_sc; o[3] = a1[nn][1][0] * inv_sc;
            o[4] = a1[nn][1][1] * inv_sc; o[5] = a1[nn][1][2] * inv_sc;
        }
    }
}

// ---------------- fused gather-reduce + lin2 + skip + gate + output ----------------
// 384 threads (12 warps/SM); Wm2 held in registers; NT=2 nodes per warp
__global__ __launch_bounds__(384, 1)
void k_final(const float* __restrict__ nf, const float* __restrict__ ea,
             const float* __restrict__ emb, const float* __restrict__ Wm1,
             const float* __restrict__ Wm2, const float* __restrict__ Wl20,
             const float* __restrict__ Wl21, const int* __restrict__ ei,
             float* __restrict__ out) {
    float* wl20 = smem_dyn;          // 16384 floats
    float* wl21 = wl20 + 16384;      // 8192
    float* wm1  = wl21 + 8192;       // 64
    float* stg  = wm1 + 64;          // 12 warps * 2 nodes * 512
    int t = threadIdx.x;             // 384
    for (int i = t; i < 16384; i += 384) wl20[i] = Wl20[i];
    for (int i = t; i < 8192; i += 384) wl21[i] = Wl21[i];
    if (t < 64) wm1[t] = Wm1[t];
    __syncthreads();

    int wid = t >> 5, lane = t & 31;
    float* stw = stg + wid * 1024;   // 2 nodes * 512
    const float inv_e = 0.35355339059327373f;   // 1/sqrt(8)
    const float inv_n = 0.35355339059327373f;   // 1/sqrt(8)
    const float inv2  = 0.08838834764831845f;   // 1/sqrt(128)
    const float is3   = 0.5773502691896258f;    // 1/sqrt(3)
    int warps = gridDim.x * 12;

    // Wm2 is loop-invariant: hoist into registers.
    // wr[p][j] = (w1,w2,w3,w4) columns for u = lane + 32p, row j
    float4 wr[2][8];
    #pragma unroll
    for (int p = 0; p < 2; p++) {
        int u = lane + p * 32;
        #pragma unroll
        for (int j = 0; j < 8; j++) {
            wr[p][j].x = Wm2[j * 256 + u];
            wr[p][j].y = Wm2[j * 256 + 64 + u];
            wr[p][j].z = Wm2[j * 256 + 128 + u];
            wr[p][j].w = Wm2[j * 256 + 192 + u];
        }
    }

    for (int nb = (blockIdx.x * 12 + wid) * 2; nb < Nn; nb += warps * 2) {
        __syncwarp();
        // ---- edge reduction phase: 2 nodes sequentially ----
        #pragma unroll 1
        for (int nn = 0; nn < 2; nn++) {
            int n = nb + nn;
            int beg = (n < Nn) ? g_off[n] : 0;
            int end = (n < Nn) ? g_off[n + 1] : 0;
            float s0a[2] = {0, 0}, s0b[2] = {0, 0};
            float s1a[2][3] = {{0, 0, 0}, {0, 0, 0}};
            float s1b[2][3] = {{0, 0, 0}, {0, 0, 0}};

            // depth-1 software pipeline of indices + data
            int e_n = 0, s_n = 0;
            float4 em0_n = {0,0,0,0}, em1_n = {0,0,0,0}, ea_n = {0,0,0,0};
            float4 ha_n = {0,0,0,0}, hb_n = {0,0,0,0};
            if (beg < end) {
                e_n = g_eperm[beg]; s_n = ei[e_n];
                if (lane < 8) {
                    const float4* ep = (const float4*)(emb + (size_t)e_n * 8);
                    em0_n = ep[0]; em1_n = ep[1];
                }
                ea_n = *(const float4*)(ea + (size_t)e_n * 4);
                const float4* hp = (const float4*)(g_h + (size_t)s_n * 256);
                ha_n = hp[lane]; hb_n = hp[lane + 32];
            }
            for (int i = beg; i < end; i++) {
                float4 em0 = em0_n, em1 = em1_n, eav = ea_n, ha = ha_n, hb = hb_n;
                if (i + 1 < end) {
                    e_n = g_eperm[i + 1]; s_n = ei[e_n];
                    if (lane < 8) {
                        const float4* ep = (const float4*)(emb + (size_t)e_n * 8);
                        em0_n = ep[0]; em1_n = ep[1];
                    }
                    ea_n = *(const float4*)(ea + (size_t)e_n * 4);
                    const float4* hp = (const float4*)(g_h + (size_t)s_n * 256);
                    ha_n = hp[lane]; hb_n = hp[lane + 32];
                }
                // hid = silu(emb @ Wm1 * inv_e): lanes 0..7 compute, broadcast
                float hv = 0.f;
                if (lane < 8) {
                    float a = em0.x * wm1[0 * 8 + lane] + em0.y * wm1[1 * 8 + lane]
                            + em0.z * wm1[2 * 8 + lane] + em0.w * wm1[3 * 8 + lane]
                            + em1.x * wm1[4 * 8 + lane] + em1.y * wm1[5 * 8 + lane]
                            + em1.z * wm1[6 * 8 + lane] + em1.w * wm1[7 * 8 + lane];
                    hv = silu_f(a * inv_e);
                }
                float hid[8];
                #pragma unroll
                for (int j = 0; j < 8; j++) hid[j] = __shfl_sync(0xffffffffu, hv, j);
                #pragma unroll
                for (int p = 0; p < 2; p++) {
                    float4 hvv = (p == 0) ? ha : hb;   // (h0, h1x, h1y, h1z)
                    float w1 = 0, w2 = 0, w3 = 0, w4 = 0;
                    #pragma unroll
                    for (int j = 0; j < 8; j++) {
                        float h = hid[j];
                        w1 += h * wr[p][j].x; w2 += h * wr[p][j].y;
                        w3 += h * wr[p][j].z; w4 += h * wr[p][j].w;
                    }
                    w1 *= inv_e; w2 *= inv_e; w3 *= inv_e; w4 *= inv_e;
                    float g0 = hvv.x, gx = hvv.y, gy = hvv.z, gz = hvv.w;
                    s0a[p] += w1 * g0 * eav.x;
                    s0b[p] += w4 * (gx * eav.y + gy * eav.z + gz * eav.w) * is3;
                    float c = w2 * g0;
                    s1a[p][0] += c * eav.y; s1a[p][1] += c * eav.z; s1a[p][2] += c * eav.w;
                    float b = w3 * eav.x;
                    s1b[p][0] += b * gx; s1b[p][1] += b * gy; s1b[p][2] += b * gz;
                }
            }
            // stage s into shared (s0[128] | s1 as k*3+d [384])
            float* st = stw + nn * 512;
            #pragma unroll
            for (int p = 0; p < 2; p++) {
                int u = lane + p * 32;
                st[u]      = s0a[p] * inv_n;
                st[64 + u] = s0b[p] * inv_n;
                #pragma unroll
                for (int d = 0; d < 3; d++) {
                    st[128 + u * 3 + d]        = s1a[p][d] * inv_n;
                    st[128 + (64 + u) * 3 + d] = s1b[p][d] * inv_n;
                }
            }
        }
        __syncwarp();

        // ---- lin2 phase: shared weight stream across 2 nodes ----
        float4 t0[2];
        #pragma unroll
        for (int nn = 0; nn < 2; nn++) t0[nn] = make_float4(0, 0, 0, 0);
        const float4* wp = (const float4*)wl20;
        #pragma unroll 4
        for (int k = 0; k < 128; k++) {
            float4 wv = wp[k * 32 + lane];
            #pragma unroll
            for (int nn = 0; nn < 2; nn++) {
                float s = stw[nn * 512 + k];
                t0[nn].x += s * wv.x; t0[nn].y += s * wv.y;
                t0[nn].z += s * wv.z; t0[nn].w += s * wv.w;
            }
        }
        float t1[2][2][3];
        #pragma unroll
        for (int nn = 0; nn < 2; nn++)
            #pragma unroll
            for (int p = 0; p < 2; p++)
                #pragma unroll
                for (int d = 0; d < 3; d++) t1[nn][p][d] = 0.f;
        const float2* wq = (const float2*)wl21;
        #pragma unroll 4
        for (int k = 0; k < 128; k++) {
            float2 wv = wq[k * 32 + lane];
            #pragma unroll
            for (int nn = 0; nn < 2; nn++) {
                const float* sb = stw + nn * 512 + 128 + k * 3;
                float y0 = sb[0], y1 = sb[1], y2 = sb[2];
                t1[nn][0][0] += wv.x * y0; t1[nn][0][1] += wv.x * y1; t1[nn][0][2] += wv.x * y2;
                t1[nn][1][0] += wv.y * y0; t1[nn][1][1] += wv.y * y1; t1[nn][1][2] += wv.y * y2;
            }
        }
        __syncwarp();

        // ---- output phase per node ----
        #pragma unroll 1
        for (int nn = 0; nn < 2; nn++) {
            int n = nb + nn;
            if (n >= Nn) continue;
            float* st = stw + nn * 512;
            float4 sc0 = ((const float4*)(g_sc + (size_t)n * 320))[lane];
            float4 tt;
            tt.x = t0[nn].x * inv2 + sc0.x; tt.y = t0[nn].y * inv2 + sc0.y;
            tt.z = t0[nn].z * inv2 + sc0.z; tt.w = t0[nn].w * inv2 + sc0.w;
            int wbase = lane * 4;
            if (wbase < 64) {
                float4 nfv = ((const float4*)(nf + (size_t)n * 256))[lane];
                float4 ov;
                ov.x = nfv.x + silu_f(tt.x); ov.y = nfv.y + silu_f(tt.y);
                ov.z = nfv.z + silu_f(tt.z); ov.w = nfv.w + silu_f(tt.w);
                ((float4*)(out + (size_t)n * 256))[lane] = ov;
            } else {
                int u = wbase - 64;
                st[u]     = silu_f(tt.x);
                st[u + 1] = silu_f(tt.y);
                st[u + 2] = silu_f(tt.z);
                st[u + 3] = silu_f(tt.w);
            }
            __syncwarp();
            int w = lane * 2;
            const float* sc1 = g_sc + (size_t)n * 320 + 128;
            float gate0 = st[w], gate1 = st[w + 1];
            float* ob = out + (size_t)n * 256;
            const float* nb2 = nf + (size_t)n * 256;
            #pragma unroll
            for (int d = 0; d < 3; d++) {
                int c0 = 64 + w * 3 + d, c1 = 64 + (w + 1) * 3 + d;
                ob[c0] = nb2[c0] + gate0 * (t1[nn][0][d] * inv2 + sc1[w * 3 + d]);
                ob[c1] = nb2[c1] + gate1 * (t1[nn][1][d] * inv2 + sc1[(w + 1) * 3 + d]);
            }
            __syncwarp();
        }
    }
}

// ---------------- host ----------------
extern "C" void kernel_launch(void* const* d_in, const int* in_sizes, int n_in,
                              void* d_out, int out_size) {
    const float* nf   = (const float*)d_in[0];
    const float* na   = (const float*)d_in[1];
    const float* ea   = (const float*)d_in[2];
    const float* emb  = (const float*)d_in[3];
    const float* W10  = (const float*)d_in[4];
    const float* W11  = (const float*)d_in[5];
    const float* Wm1  = (const float*)d_in[6];
    const float* Wm2  = (const float*)d_in[7];
    const float* Wl20 = (const float*)d_in[8];
    const float* Wl21 = (const float*)d_in[9];
    const float* Wsc0 = (const float*)d_in[10];
    const float* Wsc1 = (const float*)d_in[11];
    const int*   ei   = (const int*)d_in[12];
    float* out = (float*)d_out;

    cudaFuncSetAttribute(k_sc,    cudaFuncAttributeMaxDynamicSharedMemorySize, 229376);
    cudaFuncSetAttribute(k_final, cudaFuncAttributeMaxDynamicSharedMemorySize, 147712);

    // position 4 = k_sc so the ncu capture lands on a hot kernel
    k_zero<<<(Nn + 255) / 256, 256>>>();
    k_hist<<<512, 256>>>(ei);
    k_scan<<<1, 1024>>>();
    k_sc<<<148, 512, 229376>>>(nf, na, Wsc0, Wsc1);
    k_scatter<<<512, 256>>>(ei);
    k_h<<<1024, 256>>>(nf, W10, W11);
    k_final<<<148, 384, 147712>>>(nf, ea, emb, Wm1, Wm2, Wl20, Wl21, ei, out);
}